// round 5
// baseline (speedup 1.0000x reference)
#include <cuda_runtime.h>
#include <cuda_bf16.h>
#include <cstdint>
#include <math.h>

// Problem dims (fixed)
#define BATCH 64
#define SEQ   512
#define IDIM  256
#define HD    1024
#define MTOT  (BATCH*SEQ)      // 32768
#define RBLK  128              // CTAs in persistent recurrent kernel
#define WSTR  1028             // padded weight column stride (floats): 4112B%128=16 -> conflict-free
#define OUT_OFF ((size_t)BATCH*SEQ*HD)

typedef unsigned long long ull;

// ---------------- scratch (device globals: no allocs allowed) ----------------
__device__ float g_xp[(size_t)MTOT * HD];                 // 128 MB
__device__ float g_gate[(size_t)3 * SEQ * BATCH * HD];    // 384 MB, [g][t][b][h]
__device__ float g_h[BATCH * HD];
__device__ float g_rh[BATCH * HD];
__device__ unsigned g_bar_count;
__device__ unsigned g_bar_gen;

// ---------------- packed f32x2 helpers ----------------
__device__ __forceinline__ void ffma2(ull& d, ull a, ull b) {
    asm("fma.rn.f32x2 %0, %1, %2, %0;" : "+l"(d) : "l"(a), "l"(b));
}
__device__ __forceinline__ ull d2l(double x) { return __double_as_longlong(x); }
__device__ __forceinline__ ull dupf(float x) {
    ull d; unsigned u = __float_as_uint(x);
    asm("mov.b64 %0, {%1, %1};" : "=l"(d) : "r"(u));
    return d;
}
__device__ __forceinline__ float hadd2(ull a, ull b) {
    unsigned alo, ahi, blo, bhi;
    asm("mov.b64 {%0, %1}, %2;" : "=r"(alo), "=r"(ahi) : "l"(a));
    asm("mov.b64 {%0, %1}, %2;" : "=r"(blo), "=r"(bhi) : "l"(b));
    return (__uint_as_float(alo) + __uint_as_float(ahi)) +
           (__uint_as_float(blo) + __uint_as_float(bhi));
}

// ---------------- grid-wide barrier ----------------
__device__ __forceinline__ void grid_sync() {
    __threadfence();          // release: h/rh stores -> L2 visible
    __syncthreads();
    if (threadIdx.x == 0) {
        unsigned gen = ((volatile unsigned*)&g_bar_gen)[0];
        unsigned arrived = atomicAdd(&g_bar_count, 1u);
        if (arrived == gridDim.x - 1) {
            g_bar_count = 0;
            __threadfence();
            atomicAdd(&g_bar_gen, 1u);
        } else {
            while (((volatile unsigned*)&g_bar_gen)[0] == gen) { __nanosleep(40); }
        }
    }
    __syncthreads();
    __threadfence_block();
}

__device__ __forceinline__ float sigmoidf_(float x) {
    return 1.0f / (1.0f + __expf(-x));
}

// ---------------- SGEMM: C = A[MxK] * B[KxN] + bias, optional row remap ------
// 128x128 block, 16-deep K tile, 8x8 per thread (acc packed along i), FFMA2.
__global__ __launch_bounds__(256, 2)
void sgemm128(const float* __restrict__ A, const float* __restrict__ B,
              const float* __restrict__ bias, float* __restrict__ C,
              int M, int N, int K, int remap)
{
    __shared__ float As[2][16][128];
    __shared__ float Bs[2][16][128];

    const int tid = threadIdx.x;
    const int bm = blockIdx.y * 128;
    const int bn = blockIdx.x * 128;

    const int tm = (tid >> 4) * 8;     // 16 row-groups
    const int tn = (tid & 15) * 8;     // 16 col-groups

    ull accp[4][8];                    // [i-pair][j], f32x2 packed over rows {2i2, 2i2+1}
#pragma unroll
    for (int i = 0; i < 4; ++i)
#pragma unroll
        for (int j = 0; j < 8; ++j) accp[i][j] = 0ull;

    const int arow = tid >> 2;
    const int acol = (tid & 3) * 4;
    const int brow = tid >> 5;
    const int bcol = (tid & 31) * 4;

    const float* Ag = A + (size_t)(bm + arow) * K + acol;
    const float* Bg = B + (size_t)brow * N + bn + bcol;

    {
        float4 a0 = *(const float4*)(Ag);
        float4 a1 = *(const float4*)(Ag + (size_t)64 * K);
        float4 b0 = *(const float4*)(Bg);
        float4 b1 = *(const float4*)(Bg + (size_t)8 * N);
        As[0][acol + 0][arow] = a0.x; As[0][acol + 1][arow] = a0.y;
        As[0][acol + 2][arow] = a0.z; As[0][acol + 3][arow] = a0.w;
        As[0][acol + 0][arow + 64] = a1.x; As[0][acol + 1][arow + 64] = a1.y;
        As[0][acol + 2][arow + 64] = a1.z; As[0][acol + 3][arow + 64] = a1.w;
        *(float4*)&Bs[0][brow][bcol] = b0;
        *(float4*)&Bs[0][brow + 8][bcol] = b1;
    }
    __syncthreads();

    int buf = 0;
    for (int kt = 0; kt < K; kt += 16) {
        const int nkt = kt + 16;
        const bool more = (nkt < K);
        float4 a0, a1, b0, b1;
        if (more) {
            a0 = *(const float4*)(Ag + nkt);
            a1 = *(const float4*)(Ag + (size_t)64 * K + nkt);
            b0 = *(const float4*)(Bg + (size_t)nkt * N);
            b1 = *(const float4*)(Bg + (size_t)(nkt + 8) * N);
        }
        const float (*as)[128] = As[buf];
        const float (*bs)[128] = Bs[buf];
#pragma unroll
        for (int kk = 0; kk < 16; ++kk) {
            // A fragment rows tm..tm+7 as 4 free f32x2 packs
            const double2 pA = *(const double2*)&as[kk][tm];       // rows {tm..tm+3}
            const double2 pB = *(const double2*)&as[kk][tm + 4];   // rows {tm+4..tm+7}
            const ull pa[4] = { d2l(pA.x), d2l(pA.y), d2l(pB.x), d2l(pB.y) };
            const float4 pb0 = *(const float4*)&bs[kk][tn];
            const float4 pb1 = *(const float4*)&bs[kk][tn + 4];
            const ull pbd[8] = { dupf(pb0.x), dupf(pb0.y), dupf(pb0.z), dupf(pb0.w),
                                 dupf(pb1.x), dupf(pb1.y), dupf(pb1.z), dupf(pb1.w) };
#pragma unroll
            for (int i2 = 0; i2 < 4; ++i2)
#pragma unroll
                for (int j = 0; j < 8; ++j)
                    ffma2(accp[i2][j], pa[i2], pbd[j]);
        }
        if (more) {
            const int nb = buf ^ 1;
            As[nb][acol + 0][arow] = a0.x; As[nb][acol + 1][arow] = a0.y;
            As[nb][acol + 2][arow] = a0.z; As[nb][acol + 3][arow] = a0.w;
            As[nb][acol + 0][arow + 64] = a1.x; As[nb][acol + 1][arow + 64] = a1.y;
            As[nb][acol + 2][arow + 64] = a1.z; As[nb][acol + 3][arow + 64] = a1.w;
            *(float4*)&Bs[nb][brow][bcol] = b0;
            *(float4*)&Bs[nb][brow + 8][bcol] = b1;
        }
        __syncthreads();
        buf ^= 1;
    }

    float bl[8];
#pragma unroll
    for (int j = 0; j < 8; ++j) bl[j] = bias[bn + tn + j];

#pragma unroll
    for (int i2 = 0; i2 < 4; ++i2) {
        float r0v[8], r1v[8];
#pragma unroll
        for (int j = 0; j < 8; ++j) {
            unsigned lo, hi;
            asm("mov.b64 {%0, %1}, %2;" : "=r"(lo), "=r"(hi) : "l"(accp[i2][j]));
            r0v[j] = __uint_as_float(lo) + bl[j];
            r1v[j] = __uint_as_float(hi) + bl[j];
        }
#pragma unroll
        for (int s = 0; s < 2; ++s) {
            const int m = bm + tm + i2 * 2 + s;
            const size_t orow = remap ? ((size_t)(m & (SEQ - 1)) * BATCH + (m >> 9))
                                      : (size_t)m;
            float* crow = C + orow * N + bn + tn;
            const float* rv = s ? r1v : r0v;
            *(float4*)(crow)     = make_float4(rv[0], rv[1], rv[2], rv[3]);
            *(float4*)(crow + 4) = make_float4(rv[4], rv[5], rv[6], rv[7]);
        }
    }
}

// ---------------- persistent recurrent kernel ----------------
// 128 CTAs x 256 threads. CTA owns 8 H-columns; weights in padded smem
// (conflict-free LDS.128). h/rh via L2 (.cg) double-buffered; FFMA2 math.
__global__ __launch_bounds__(256, 1)
void gru_rec(const float* __restrict__ Wzh, const float* __restrict__ Wrh,
             const float* __restrict__ Wnh, float* __restrict__ out)
{
    extern __shared__ float smem[];
    float* wz_s = smem;                  // 8 cols x WSTR
    float* wr_s = smem + 8 * WSTR;
    float* wn_s = smem + 16 * WSTR;

    const int tid = threadIdx.x;
    const int c0 = blockIdx.x * 8;

    for (int i = tid; i < 8 * HD; i += 256) {
        const int k = i >> 3, c = i & 7;
        wz_s[c * WSTR + k] = Wzh[(size_t)k * HD + c0 + c];
        wr_s[c * WSTR + k] = Wrh[(size_t)k * HD + c0 + c];
        wn_s[c * WSTR + k] = Wnh[(size_t)k * HD + c0 + c];
    }
    for (int i = blockIdx.x * 256 + tid; i < BATCH * HD; i += RBLK * 256)
        g_h[i] = 0.0f;
    grid_sync();

    const int cl  = tid & 7;
    const int col = c0 + cl;
    const int r0  = (tid >> 3) * 2;     // batch rows r0, r0+1
    const double2* wz2 = (const double2*)(wz_s + cl * WSTR);   // 16B elems, 256/row
    const double2* wr2 = (const double2*)(wr_s + cl * WSTR);
    const double2* wn2 = (const double2*)(wn_s + cl * WSTR);

    const float* gz = g_gate;
    const float* gr = g_gate + (size_t)SEQ * BATCH * HD;
    const float* gn = g_gate + (size_t)2 * SEQ * BATCH * HD;

    const double2* h0p = (const double2*)(g_h + r0 * HD);
    const double2* h1p = (const double2*)(g_h + (r0 + 1) * HD);
    const double2* rh0p = (const double2*)(g_rh + r0 * HD);
    const double2* rh1p = (const double2*)(g_rh + (r0 + 1) * HD);

    for (int t = 0; t < SEQ; ++t) {
        // ---- Phase A: z = sig(xz + h@Wz_h), r = sig(xr + h@Wr_h), rh = r*h
        ull az0a = 0, az0b = 0, az1a = 0, az1b = 0;
        ull ar0a = 0, ar0b = 0, ar1a = 0, ar1b = 0;
        double2 A0[4], A1[4], B0[4], B1[4];

#define LOADH(b0, b1, base) { _Pragma("unroll") \
        for (int j = 0; j < 4; ++j) { b0[j] = __ldcg(h0p + (base) + j); b1[j] = __ldcg(h1p + (base) + j); } }
#define COMPA(b0, b1, base) { _Pragma("unroll") \
        for (int j = 0; j < 4; ++j) { \
            const double2 wz = wz2[(base) + j], wr = wr2[(base) + j]; \
            const ull h0l = d2l(b0[j].x), h0h = d2l(b0[j].y); \
            const ull h1l = d2l(b1[j].x), h1h = d2l(b1[j].y); \
            ffma2(az0a, h0l, d2l(wz.x)); ffma2(az0b, h0h, d2l(wz.y)); \
            ffma2(az1a, h1l, d2l(wz.x)); ffma2(az1b, h1h, d2l(wz.y)); \
            ffma2(ar0a, h0l, d2l(wr.x)); ffma2(ar0b, h0h, d2l(wr.y)); \
            ffma2(ar1a, h1l, d2l(wr.x)); ffma2(ar1b, h1h, d2l(wr.y)); } }

        LOADH(A0, A1, 0);
        for (int blk = 0; blk < 64; blk += 2) {          // 64 blocks of 4x16B (16 k each)
            LOADH(B0, B1, (blk + 1) * 4);
            COMPA(A0, A1, blk * 4);
            if (blk + 2 < 64) { LOADH(A0, A1, (blk + 2) * 4); }
            COMPA(B0, B1, (blk + 1) * 4);
        }

        const int gidx0 = (t * BATCH + r0) * HD + col;
        const int gidx1 = gidx0 + HD;
        const float z0 = sigmoidf_(hadd2(az0a, az0b) + __ldg(gz + gidx0));
        const float z1 = sigmoidf_(hadd2(az1a, az1b) + __ldg(gz + gidx1));
        const float rv0 = sigmoidf_(hadd2(ar0a, ar0b) + __ldg(gr + gidx0));
        const float rv1 = sigmoidf_(hadd2(ar1a, ar1b) + __ldg(gr + gidx1));
        const float h0v = __ldcg(g_h + r0 * HD + col);
        const float h1v = __ldcg(g_h + (r0 + 1) * HD + col);
        g_rh[r0 * HD + col]       = rv0 * h0v;
        g_rh[(r0 + 1) * HD + col] = rv1 * h1v;

        grid_sync();

        // ---- Phase B: n = tanh(xn + rh@Wn_h), h' = (1-z)n + z h
        ull an0a = 0, an0b = 0, an1a = 0, an1b = 0;
        double2 C0[4], C1[4], D0[4], D1[4];

#define LOADR(b0, b1, base) { _Pragma("unroll") \
        for (int j = 0; j < 4; ++j) { b0[j] = __ldcg(rh0p + (base) + j); b1[j] = __ldcg(rh1p + (base) + j); } }
#define COMPB(b0, b1, base) { _Pragma("unroll") \
        for (int j = 0; j < 4; ++j) { \
            const double2 wn = wn2[(base) + j]; \
            ffma2(an0a, d2l(b0[j].x), d2l(wn.x)); ffma2(an0b, d2l(b0[j].y), d2l(wn.y)); \
            ffma2(an1a, d2l(b1[j].x), d2l(wn.x)); ffma2(an1b, d2l(b1[j].y), d2l(wn.y)); } }

        LOADR(C0, C1, 0);
        for (int blk = 0; blk < 64; blk += 2) {
            LOADR(D0, D1, (blk + 1) * 4);
            COMPB(C0, C1, blk * 4);
            if (blk + 2 < 64) { LOADR(C0, C1, (blk + 2) * 4); }
            COMPB(D0, D1, (blk + 1) * 4);
        }

        const float n0 = tanhf(hadd2(an0a, an0b) + __ldg(gn + gidx0));
        const float n1 = tanhf(hadd2(an1a, an1b) + __ldg(gn + gidx1));
        const float hn0 = (1.0f - z0) * n0 + z0 * h0v;
        const float hn1 = (1.0f - z1) * n1 + z1 * h1v;
        g_h[r0 * HD + col]       = hn0;
        g_h[(r0 + 1) * HD + col] = hn1;
        out[((size_t)r0 * SEQ + t) * HD + col]       = hn0;
        out[((size_t)(r0 + 1) * SEQ + t) * HD + col] = hn1;
        if (t == SEQ - 1) {
            out[OUT_OFF + (size_t)r0 * HD + col]       = hn0;
            out[OUT_OFF + (size_t)(r0 + 1) * HD + col] = hn1;
        }
        grid_sync();
    }
}

// ---------------- launch ----------------
extern "C" void kernel_launch(void* const* d_in, const int* in_sizes, int n_in,
                              void* d_out, int out_size)
{
    const float* x  = (const float*)d_in[0];
    const float* Wi = (const float*)d_in[1];
    const float* bi = (const float*)d_in[2];
    const float* Wz = (const float*)d_in[3];
    const float* bz = (const float*)d_in[4];
    const float* Wr = (const float*)d_in[5];
    const float* br = (const float*)d_in[6];
    const float* Wn = (const float*)d_in[7];
    const float* bn = (const float*)d_in[8];
    float* out = (float*)d_out;

    float* xp;   cudaGetSymbolAddress((void**)&xp,   g_xp);
    float* gate; cudaGetSymbolAddress((void**)&gate, g_gate);

    const dim3 gg(HD / 128, MTOT / 128);   // (8, 256)

    // xp = x @ Wi + bi
    sgemm128<<<gg, 256>>>(x, Wi, bi, xp, MTOT, HD, IDIM, 0);
    // gates (time-major): xz, xr, xn  (W*[0:H] = x-part of each weight)
    sgemm128<<<gg, 256>>>(xp, Wz, bz, gate,                                MTOT, HD, HD, 1);
    sgemm128<<<gg, 256>>>(xp, Wr, br, gate + (size_t)SEQ * BATCH * HD,     MTOT, HD, HD, 1);
    sgemm128<<<gg, 256>>>(xp, Wn, bn, gate + (size_t)2 * SEQ * BATCH * HD, MTOT, HD, HD, 1);

    // persistent recurrence: weights' h-part starts at row HD
    cudaFuncSetAttribute(gru_rec, cudaFuncAttributeMaxDynamicSharedMemorySize, 24 * WSTR * 4);
    gru_rec<<<RBLK, 256, 24 * WSTR * 4>>>(Wz + (size_t)HD * HD,
                                          Wr + (size_t)HD * HD,
                                          Wn + (size_t)HD * HD, out);
}

// round 6
// speedup vs baseline: 1.0631x; 1.0631x over previous
#include <cuda_runtime.h>
#include <cuda_bf16.h>
#include <cstdint>
#include <math.h>

// Problem dims (fixed)
#define BATCH 64
#define SEQ   512
#define IDIM  256
#define HD    1024
#define MTOT  (BATCH*SEQ)      // 32768
#define RBLK  128              // CTAs in persistent recurrent kernel
#define WSTR  1028             // padded weight column stride (floats): 4112B%128=16 -> conflict-free
#define OUT_OFF ((size_t)BATCH*SEQ*HD)

typedef unsigned long long ull;

// ---------------- scratch (device globals: no allocs allowed) ----------------
__device__ float g_xp[(size_t)MTOT * HD];                 // 128 MB
__device__ float g_gate[(size_t)3 * SEQ * BATCH * HD];    // 384 MB, [g][t][b][h]
__device__ float g_h[BATCH * HD];
__device__ float g_rh[BATCH * HD];
__device__ unsigned g_bar_count;
__device__ unsigned g_bar_gen;

// ---------------- packed f32x2 helpers ----------------
__device__ __forceinline__ void ffma2(ull& d, ull a, ull b) {
    asm("fma.rn.f32x2 %0, %1, %2, %0;" : "+l"(d) : "l"(a), "l"(b));
}
__device__ __forceinline__ ull d2l(double x) { return __double_as_longlong(x); }
__device__ __forceinline__ ull dupf(float x) {
    ull d; unsigned u = __float_as_uint(x);
    asm("mov.b64 %0, {%1, %1};" : "=l"(d) : "r"(u));
    return d;
}
__device__ __forceinline__ float hadd2(ull a, ull b) {
    unsigned alo, ahi, blo, bhi;
    asm("mov.b64 {%0, %1}, %2;" : "=r"(alo), "=r"(ahi) : "l"(a));
    asm("mov.b64 {%0, %1}, %2;" : "=r"(blo), "=r"(bhi) : "l"(b));
    return (__uint_as_float(alo) + __uint_as_float(ahi)) +
           (__uint_as_float(blo) + __uint_as_float(bhi));
}

// ---------------- grid-wide barrier ----------------
__device__ __forceinline__ void grid_sync() {
    __threadfence();          // release: h/rh stores -> L2 visible
    __syncthreads();
    if (threadIdx.x == 0) {
        unsigned gen = ((volatile unsigned*)&g_bar_gen)[0];
        unsigned arrived = atomicAdd(&g_bar_count, 1u);
        if (arrived == gridDim.x - 1) {
            g_bar_count = 0;
            __threadfence();
            atomicAdd(&g_bar_gen, 1u);
        } else {
            while (((volatile unsigned*)&g_bar_gen)[0] == gen) { __nanosleep(20); }
        }
    }
    __syncthreads();
    __threadfence_block();
}

__device__ __forceinline__ float sigmoidf_(float x) {
    return 1.0f / (1.0f + __expf(-x));
}

// ---------------- SGEMM: C = A[MxK] * B[KxN] + bias, optional row remap ------
// 128x128 block, 16-deep K tile, 8x8 per thread (acc packed along i), FFMA2.
__global__ __launch_bounds__(256, 2)
void sgemm128(const float* __restrict__ A, const float* __restrict__ B,
              const float* __restrict__ bias, float* __restrict__ C,
              int M, int N, int K, int remap)
{
    __shared__ float As[2][16][128];
    __shared__ float Bs[2][16][128];

    const int tid = threadIdx.x;
    const int bm = blockIdx.y * 128;
    const int bn = blockIdx.x * 128;

    const int tm = (tid >> 4) * 8;
    const int tn = (tid & 15) * 8;

    ull accp[4][8];
#pragma unroll
    for (int i = 0; i < 4; ++i)
#pragma unroll
        for (int j = 0; j < 8; ++j) accp[i][j] = 0ull;

    const int arow = tid >> 2;
    const int acol = (tid & 3) * 4;
    const int brow = tid >> 5;
    const int bcol = (tid & 31) * 4;

    const float* Ag = A + (size_t)(bm + arow) * K + acol;
    const float* Bg = B + (size_t)brow * N + bn + bcol;

    {
        float4 a0 = *(const float4*)(Ag);
        float4 a1 = *(const float4*)(Ag + (size_t)64 * K);
        float4 b0 = *(const float4*)(Bg);
        float4 b1 = *(const float4*)(Bg + (size_t)8 * N);
        As[0][acol + 0][arow] = a0.x; As[0][acol + 1][arow] = a0.y;
        As[0][acol + 2][arow] = a0.z; As[0][acol + 3][arow] = a0.w;
        As[0][acol + 0][arow + 64] = a1.x; As[0][acol + 1][arow + 64] = a1.y;
        As[0][acol + 2][arow + 64] = a1.z; As[0][acol + 3][arow + 64] = a1.w;
        *(float4*)&Bs[0][brow][bcol] = b0;
        *(float4*)&Bs[0][brow + 8][bcol] = b1;
    }
    __syncthreads();

    int buf = 0;
    for (int kt = 0; kt < K; kt += 16) {
        const int nkt = kt + 16;
        const bool more = (nkt < K);
        float4 a0, a1, b0, b1;
        if (more) {
            a0 = *(const float4*)(Ag + nkt);
            a1 = *(const float4*)(Ag + (size_t)64 * K + nkt);
            b0 = *(const float4*)(Bg + (size_t)nkt * N);
            b1 = *(const float4*)(Bg + (size_t)(nkt + 8) * N);
        }
        const float (*as)[128] = As[buf];
        const float (*bs)[128] = Bs[buf];
#pragma unroll
        for (int kk = 0; kk < 16; ++kk) {
            const double2 pA = *(const double2*)&as[kk][tm];
            const double2 pB = *(const double2*)&as[kk][tm + 4];
            const ull pa[4] = { d2l(pA.x), d2l(pA.y), d2l(pB.x), d2l(pB.y) };
            const float4 pb0 = *(const float4*)&bs[kk][tn];
            const float4 pb1 = *(const float4*)&bs[kk][tn + 4];
            const ull pbd[8] = { dupf(pb0.x), dupf(pb0.y), dupf(pb0.z), dupf(pb0.w),
                                 dupf(pb1.x), dupf(pb1.y), dupf(pb1.z), dupf(pb1.w) };
#pragma unroll
            for (int i2 = 0; i2 < 4; ++i2)
#pragma unroll
                for (int j = 0; j < 8; ++j)
                    ffma2(accp[i2][j], pa[i2], pbd[j]);
        }
        if (more) {
            const int nb = buf ^ 1;
            As[nb][acol + 0][arow] = a0.x; As[nb][acol + 1][arow] = a0.y;
            As[nb][acol + 2][arow] = a0.z; As[nb][acol + 3][arow] = a0.w;
            As[nb][acol + 0][arow + 64] = a1.x; As[nb][acol + 1][arow + 64] = a1.y;
            As[nb][acol + 2][arow + 64] = a1.z; As[nb][acol + 3][arow + 64] = a1.w;
            *(float4*)&Bs[nb][brow][bcol] = b0;
            *(float4*)&Bs[nb][brow + 8][bcol] = b1;
        }
        __syncthreads();
        buf ^= 1;
    }

    float bl[8];
#pragma unroll
    for (int j = 0; j < 8; ++j) bl[j] = bias[bn + tn + j];

#pragma unroll
    for (int i2 = 0; i2 < 4; ++i2) {
        float r0v[8], r1v[8];
#pragma unroll
        for (int j = 0; j < 8; ++j) {
            unsigned lo, hi;
            asm("mov.b64 {%0, %1}, %2;" : "=r"(lo), "=r"(hi) : "l"(accp[i2][j]));
            r0v[j] = __uint_as_float(lo) + bl[j];
            r1v[j] = __uint_as_float(hi) + bl[j];
        }
#pragma unroll
        for (int s = 0; s < 2; ++s) {
            const int m = bm + tm + i2 * 2 + s;
            const size_t orow = remap ? ((size_t)(m & (SEQ - 1)) * BATCH + (m >> 9))
                                      : (size_t)m;
            float* crow = C + orow * N + bn + tn;
            const float* rv = s ? r1v : r0v;
            *(float4*)(crow)     = make_float4(rv[0], rv[1], rv[2], rv[3]);
            *(float4*)(crow + 4) = make_float4(rv[4], rv[5], rv[6], rv[7]);
        }
    }
}

// ---------------- persistent recurrent kernel ----------------
// 128 CTAs x 256 threads. CTA owns 8 H-columns; weights in padded smem.
// Depth-4 register prefetch pipeline on h/rh streams (32 LDG.128 in flight).
__global__ __launch_bounds__(256, 1)
void gru_rec(const float* __restrict__ Wzh, const float* __restrict__ Wrh,
             const float* __restrict__ Wnh, float* __restrict__ out)
{
    extern __shared__ float smem[];
    float* wz_s = smem;                  // 8 cols x WSTR
    float* wr_s = smem + 8 * WSTR;
    float* wn_s = smem + 16 * WSTR;

    const int tid = threadIdx.x;
    const int c0 = blockIdx.x * 8;

    for (int i = tid; i < 8 * HD; i += 256) {
        const int k = i >> 3, c = i & 7;
        wz_s[c * WSTR + k] = Wzh[(size_t)k * HD + c0 + c];
        wr_s[c * WSTR + k] = Wrh[(size_t)k * HD + c0 + c];
        wn_s[c * WSTR + k] = Wnh[(size_t)k * HD + c0 + c];
    }
    for (int i = blockIdx.x * 256 + tid; i < BATCH * HD; i += RBLK * 256)
        g_h[i] = 0.0f;
    grid_sync();

    const int cl  = tid & 7;
    const int col = c0 + cl;
    const int r0  = (tid >> 3) * 2;     // batch rows r0, r0+1
    const double2* wz2 = (const double2*)(wz_s + cl * WSTR);
    const double2* wr2 = (const double2*)(wr_s + cl * WSTR);
    const double2* wn2 = (const double2*)(wn_s + cl * WSTR);

    const float* gz = g_gate;
    const float* gr = g_gate + (size_t)SEQ * BATCH * HD;
    const float* gn = g_gate + (size_t)2 * SEQ * BATCH * HD;

    const double2* h0p  = (const double2*)(g_h + r0 * HD);
    const double2* h1p  = (const double2*)(g_h + (r0 + 1) * HD);
    const double2* rh0p = (const double2*)(g_rh + r0 * HD);
    const double2* rh1p = (const double2*)(g_rh + (r0 + 1) * HD);

    // pipeline buffers: 4 stages x 4 double2 per row = 32 double2 total
    double2 P0[4][4], P1[4][4];

    for (int t = 0; t < SEQ; ++t) {
        // ---- Phase A: z = sig(xz + h@Wz_h), r = sig(xr + h@Wr_h), rh = r*h
        const int gidx0 = (t * BATCH + r0) * HD + col;
        const int gidx1 = gidx0 + HD;

        // early scalar loads (gates immutable; h row elements)
        const float xz0 = __ldg(gz + gidx0);
        const float xz1 = __ldg(gz + gidx1);
        const float xr0 = __ldg(gr + gidx0);
        const float xr1 = __ldg(gr + gidx1);
        const float h0v = __ldcg(g_h + r0 * HD + col);
        const float h1v = __ldcg(g_h + (r0 + 1) * HD + col);

        // prime pipeline: stages 0..3 = units 0..3
#pragma unroll
        for (int s = 0; s < 4; ++s)
#pragma unroll
            for (int j = 0; j < 4; ++j) {
                P0[s][j] = __ldcg(h0p + s * 4 + j);
                P1[s][j] = __ldcg(h1p + s * 4 + j);
            }

        ull az0a = 0, az0b = 0, az1a = 0, az1b = 0;
        ull ar0a = 0, ar0b = 0, ar1a = 0, ar1b = 0;

#pragma unroll 4
        for (int u = 0; u < 64; ++u) {
            const int s = u & 3;
#pragma unroll
            for (int j = 0; j < 4; ++j) {
                const double2 wz = wz2[u * 4 + j], wr = wr2[u * 4 + j];
                const ull h0l = d2l(P0[s][j].x), h0h = d2l(P0[s][j].y);
                const ull h1l = d2l(P1[s][j].x), h1h = d2l(P1[s][j].y);
                ffma2(az0a, h0l, d2l(wz.x)); ffma2(az0b, h0h, d2l(wz.y));
                ffma2(az1a, h1l, d2l(wz.x)); ffma2(az1b, h1h, d2l(wz.y));
                ffma2(ar0a, h0l, d2l(wr.x)); ffma2(ar0b, h0h, d2l(wr.y));
                ffma2(ar1a, h1l, d2l(wr.x)); ffma2(ar1b, h1h, d2l(wr.y));
            }
            if (u + 4 < 64) {
#pragma unroll
                for (int j = 0; j < 4; ++j) {
                    P0[s][j] = __ldcg(h0p + (u + 4) * 4 + j);
                    P1[s][j] = __ldcg(h1p + (u + 4) * 4 + j);
                }
            }
        }

        const float z0 = sigmoidf_(hadd2(az0a, az0b) + xz0);
        const float z1 = sigmoidf_(hadd2(az1a, az1b) + xz1);
        const float rv0 = sigmoidf_(hadd2(ar0a, ar0b) + xr0);
        const float rv1 = sigmoidf_(hadd2(ar1a, ar1b) + xr1);
        g_rh[r0 * HD + col]       = rv0 * h0v;
        g_rh[(r0 + 1) * HD + col] = rv1 * h1v;

        grid_sync();

        // ---- Phase B: n = tanh(xn + rh@Wn_h), h' = (1-z)n + z h
        const float xn0 = __ldg(gn + gidx0);
        const float xn1 = __ldg(gn + gidx1);

#pragma unroll
        for (int s = 0; s < 4; ++s)
#pragma unroll
            for (int j = 0; j < 4; ++j) {
                P0[s][j] = __ldcg(rh0p + s * 4 + j);
                P1[s][j] = __ldcg(rh1p + s * 4 + j);
            }

        ull an0a = 0, an0b = 0, an1a = 0, an1b = 0;

#pragma unroll 4
        for (int u = 0; u < 64; ++u) {
            const int s = u & 3;
#pragma unroll
            for (int j = 0; j < 4; ++j) {
                const double2 wn = wn2[u * 4 + j];
                ffma2(an0a, d2l(P0[s][j].x), d2l(wn.x));
                ffma2(an0b, d2l(P0[s][j].y), d2l(wn.y));
                ffma2(an1a, d2l(P1[s][j].x), d2l(wn.x));
                ffma2(an1b, d2l(P1[s][j].y), d2l(wn.y));
            }
            if (u + 4 < 64) {
#pragma unroll
                for (int j = 0; j < 4; ++j) {
                    P0[s][j] = __ldcg(rh0p + (u + 4) * 4 + j);
                    P1[s][j] = __ldcg(rh1p + (u + 4) * 4 + j);
                }
            }
        }

        const float n0 = tanhf(hadd2(an0a, an0b) + xn0);
        const float n1 = tanhf(hadd2(an1a, an1b) + xn1);
        const float hn0 = (1.0f - z0) * n0 + z0 * h0v;
        const float hn1 = (1.0f - z1) * n1 + z1 * h1v;
        g_h[r0 * HD + col]       = hn0;
        g_h[(r0 + 1) * HD + col] = hn1;
        out[((size_t)r0 * SEQ + t) * HD + col]       = hn0;
        out[((size_t)(r0 + 1) * SEQ + t) * HD + col] = hn1;
        if (t == SEQ - 1) {
            out[OUT_OFF + (size_t)r0 * HD + col]       = hn0;
            out[OUT_OFF + (size_t)(r0 + 1) * HD + col] = hn1;
        }
        grid_sync();
    }
}

// ---------------- launch ----------------
extern "C" void kernel_launch(void* const* d_in, const int* in_sizes, int n_in,
                              void* d_out, int out_size)
{
    const float* x  = (const float*)d_in[0];
    const float* Wi = (const float*)d_in[1];
    const float* bi = (const float*)d_in[2];
    const float* Wz = (const float*)d_in[3];
    const float* bz = (const float*)d_in[4];
    const float* Wr = (const float*)d_in[5];
    const float* br = (const float*)d_in[6];
    const float* Wn = (const float*)d_in[7];
    const float* bn = (const float*)d_in[8];
    float* out = (float*)d_out;

    float* xp;   cudaGetSymbolAddress((void**)&xp,   g_xp);
    float* gate; cudaGetSymbolAddress((void**)&gate, g_gate);

    const dim3 gg(HD / 128, MTOT / 128);   // (8, 256)

    sgemm128<<<gg, 256>>>(x, Wi, bi, xp, MTOT, HD, IDIM, 0);
    sgemm128<<<gg, 256>>>(xp, Wz, bz, gate,                                MTOT, HD, HD, 1);
    sgemm128<<<gg, 256>>>(xp, Wr, br, gate + (size_t)SEQ * BATCH * HD,     MTOT, HD, HD, 1);
    sgemm128<<<gg, 256>>>(xp, Wn, bn, gate + (size_t)2 * SEQ * BATCH * HD, MTOT, HD, HD, 1);

    cudaFuncSetAttribute(gru_rec, cudaFuncAttributeMaxDynamicSharedMemorySize, 24 * WSTR * 4);
    gru_rec<<<RBLK, 256, 24 * WSTR * 4>>>(Wz + (size_t)HD * HD,
                                          Wr + (size_t)HD * HD,
                                          Wn + (size_t)HD * HD, out);
}